// round 15
// baseline (speedup 1.0000x reference)
#include <cuda_runtime.h>
#include <cuda_bf16.h>
#include <cstdint>
#include <cstddef>

// Problem constants
#define BB 4
#define CC 256
#define CI 128
#define NNq 8192      // T*H*W = 8*32*32
#define N2 2048       // T*16*16
#define BN_EPS 1e-5f

typedef unsigned long long ull;

// Scratch: single device-global buffer (no allocations allowed).
#define SZ_FULL (BB * NNq * CI)   // 4,194,304 floats
#define SZ_POOL (BB * N2 * CI)    // 1,048,576 floats
#define OFF_Q  0
#define OFF_PF (SZ_FULL)
#define OFF_GF (2 * SZ_FULL)
#define OFF_K  (3 * SZ_FULL)                 // [b][m][ci]
#define OFF_V  (3 * SZ_FULL + SZ_POOL)       // [b][m][ci]
#define OFF_Y  (3 * SZ_FULL + 2 * SZ_POOL)

__device__ __align__(16) float g_buf[3 * SZ_FULL + 2 * SZ_POOL + SZ_FULL];

// ---------------------------------------------------------------------------
// f32x2 packed-FMA helpers (for proj / final kernels)
// ---------------------------------------------------------------------------
__device__ __forceinline__ ull dup2(float a) {
    ull r; asm("mov.b64 %0, {%1, %1};" : "=l"(r) : "f"(a)); return r;
}
__device__ __forceinline__ void fma2(ull& d, ull a, ull b) {
    asm("fma.rn.f32x2 %0, %1, %2, %0;" : "+l"(d) : "l"(a), "l"(b));
}
__device__ __forceinline__ void unpk(ull v, float& lo, float& hi) {
    asm("mov.b64 {%0, %1}, %2;" : "=f"(lo), "=f"(hi) : "l"(v));
}

// ---------------------------------------------------------------------------
// mma.sync / ldmatrix helpers
// ---------------------------------------------------------------------------
__device__ __forceinline__ void ldsm4(uint32_t* r, uint32_t addr) {
    asm volatile("ldmatrix.sync.aligned.m8n8.x4.shared.b16 {%0,%1,%2,%3}, [%4];\n"
                 : "=r"(r[0]), "=r"(r[1]), "=r"(r[2]), "=r"(r[3]) : "r"(addr));
}
__device__ __forceinline__ void ldsm4t(uint32_t* r, uint32_t addr) {
    asm volatile("ldmatrix.sync.aligned.m8n8.x4.trans.shared.b16 {%0,%1,%2,%3}, [%4];\n"
                 : "=r"(r[0]), "=r"(r[1]), "=r"(r[2]), "=r"(r[3]) : "r"(addr));
}
__device__ __forceinline__ void mma16816(float* d, const uint32_t* a,
                                         uint32_t b0, uint32_t b1) {
    asm volatile(
        "mma.sync.aligned.m16n8k16.row.col.f32.bf16.bf16.f32 "
        "{%0,%1,%2,%3}, {%4,%5,%6,%7}, {%8,%9}, {%0,%1,%2,%3};\n"
        : "+f"(d[0]), "+f"(d[1]), "+f"(d[2]), "+f"(d[3])
        : "r"(a[0]), "r"(a[1]), "r"(a[2]), "r"(a[3]), "r"(b0), "r"(b1));
}
__device__ __forceinline__ uint32_t b2u(__nv_bfloat162 v) {
    return *reinterpret_cast<uint32_t*>(&v);
}

// ---------------------------------------------------------------------------
// Projection GEMM (f32x2): out[b][n][ci] = sum_c x[b][c][n]*w[ci][c] + bias
// ---------------------------------------------------------------------------
template <int OFF>
__global__ void __launch_bounds__(256)
proj_kernel(const float* __restrict__ x,
            const float* __restrict__ w,
            const float* __restrict__ bias)
{
    __shared__ __align__(16) float as[16][132];
    __shared__ __align__(16) float bs[16][132];

    const int b   = blockIdx.y;
    const int n0  = blockIdx.x * 128;
    const int tid = threadIdx.x;
    const int txx = tid & 15;
    const int tyy = tid >> 4;

    ull acc[8][4];
#pragma unroll
    for (int i = 0; i < 8; i++)
#pragma unroll
        for (int j = 0; j < 4; j++) acc[i][j] = 0ULL;

    const float* xb = x + (size_t)b * CC * NNq;

    for (int c0 = 0; c0 < CC; c0 += 16) {
#pragma unroll
        for (int r = 0; r < 8; r++) {
            int e = r * 256 + tid;
            int k = e >> 7, n = e & 127;
            as[k][n] = xb[(size_t)(c0 + k) * NNq + n0 + n];
        }
#pragma unroll
        for (int r = 0; r < 8; r++) {
            int e = r * 256 + tid;
            int ci = e >> 4, k = e & 15;
            bs[k][ci] = w[ci * CC + c0 + k];
        }
        __syncthreads();

#pragma unroll
        for (int k = 0; k < 16; k++) {
            float4 a0 = *(const float4*)&as[k][tyy * 4];
            float4 a1 = *(const float4*)&as[k][tyy * 4 + 64];
            ulonglong2 b0 = *(const ulonglong2*)&bs[k][txx * 4];
            ulonglong2 b1 = *(const ulonglong2*)&bs[k][txx * 4 + 64];
            float av[8] = {a0.x, a0.y, a0.z, a0.w, a1.x, a1.y, a1.z, a1.w};
#pragma unroll
            for (int i = 0; i < 8; i++) {
                ull d = dup2(av[i]);
                fma2(acc[i][0], d, b0.x);
                fma2(acc[i][1], d, b0.y);
                fma2(acc[i][2], d, b1.x);
                fma2(acc[i][3], d, b1.y);
            }
        }
        __syncthreads();
    }

    float bvv[8];
#pragma unroll
    for (int j = 0; j < 4; j++) {
        bvv[j]     = bias[txx * 4 + j];
        bvv[j + 4] = bias[txx * 4 + 64 + j];
    }
    float* out = g_buf + OFF;
#pragma unroll
    for (int i = 0; i < 8; i++) {
        int n = n0 + ((i < 4) ? (tyy * 4 + i) : (tyy * 4 + 64 + (i - 4)));
        float* o = out + (size_t)(b * NNq + n) * CI;
        float f[8];
        unpk(acc[i][0], f[0], f[1]); unpk(acc[i][1], f[2], f[3]);
        unpk(acc[i][2], f[4], f[5]); unpk(acc[i][3], f[6], f[7]);
        float4 v0, v1;
        v0.x = f[0] + bvv[0]; v0.y = f[1] + bvv[1];
        v0.z = f[2] + bvv[2]; v0.w = f[3] + bvv[3];
        v1.x = f[4] + bvv[4]; v1.y = f[5] + bvv[5];
        v1.z = f[6] + bvv[6]; v1.w = f[7] + bvv[7];
        *(float4*)&o[txx * 4]      = v0;
        *(float4*)&o[txx * 4 + 64] = v1;
    }
}

// ---------------------------------------------------------------------------
// 2x2 max pool: phi -> K [b][m][ci],  g -> V [b][m][ci]
// ---------------------------------------------------------------------------
__global__ void __launch_bounds__(256)
pool_kernel()
{
    int e = blockIdx.x * 256 + threadIdx.x;
    if (e >= BB * N2 * CI) return;
    int ci = e & 127;
    int r  = e >> 7;
    int m  = r & (N2 - 1);
    int b  = r >> 11;
    int t  = m >> 8;
    int h2 = (m >> 4) & 15;
    int w2 = m & 15;
    int nb = t * 1024 + (h2 * 2) * 32 + w2 * 2;
    size_t base = ((size_t)b * NNq + nb) * CI + ci;

    const float* pf = g_buf + OFF_PF;
    const float* gf = g_buf + OFF_GF;
    float p0 = pf[base], p1 = pf[base + CI], p2 = pf[base + 32 * CI], p3 = pf[base + 33 * CI];
    float q0 = gf[base], q1 = gf[base + CI], q2 = gf[base + 32 * CI], q3 = gf[base + 33 * CI];
    g_buf[OFF_K + e] = fmaxf(fmaxf(p0, p1), fmaxf(p2, p3));
    g_buf[OFF_V + e] = fmaxf(fmaxf(q0, q1), fmaxf(q2, q3));
}

// ---------------------------------------------------------------------------
// Tensor-core flash attention, bf16 3-MMA split precision.
// CTA: 256 threads (8 warps), 256 queries (2 tiles of 128), kv-blocks of 64.
// Warp w owns q rows [w*16, w*16+16) of each q-tile.
// smem (bf16, row stride 136): Qhi[256], Qlo[256], Khi/Klo[64], Vhi/Vlo[64].
// ---------------------------------------------------------------------------
#define SQH 0
#define SQL 34816            // 256*136
#define SKH 69632
#define SKL (69632 + 8704)   // 64*136
#define SVH (69632 + 17408)
#define SVL (69632 + 26112)
#define SM_ELEMS (69632 + 34816)
#define SM_BYTES (SM_ELEMS * 2)

extern __shared__ __align__(16) __nv_bfloat16 smem_bf[];

__device__ __forceinline__ void split_store4(float4 v, int idx, int hiOff, int loOff) {
    __nv_bfloat162 h01 = __floats2bfloat162_rn(v.x, v.y);
    __nv_bfloat162 h23 = __floats2bfloat162_rn(v.z, v.w);
    float r0 = v.x - __bfloat162float(h01.x);
    float r1 = v.y - __bfloat162float(h01.y);
    float r2 = v.z - __bfloat162float(h23.x);
    float r3 = v.w - __bfloat162float(h23.y);
    *(__nv_bfloat162*)&smem_bf[hiOff + idx]     = h01;
    *(__nv_bfloat162*)&smem_bf[hiOff + idx + 2] = h23;
    *(__nv_bfloat162*)&smem_bf[loOff + idx]     = __floats2bfloat162_rn(r0, r1);
    *(__nv_bfloat162*)&smem_bf[loOff + idx + 2] = __floats2bfloat162_rn(r2, r3);
}

__global__ void __launch_bounds__(256, 1)
attn_kernel()
{
    const int b    = blockIdx.y;
    const int q0   = blockIdx.x * 256;
    const int tid  = threadIdx.x;
    const int warp = tid >> 5;
    const int lane = tid & 31;

    const float* Qb = g_buf + OFF_Q + ((size_t)b * NNq + q0) * CI;
    const float* Kb = g_buf + OFF_K + (size_t)b * N2 * CI;
    const float* Vb = g_buf + OFF_V + (size_t)b * N2 * CI;

    // ---- stage Q (256 rows), split hi/lo ----
#pragma unroll 4
    for (int i = 0; i < 32; i++) {
        int e = i * 256 + tid;
        int row = e >> 5;
        int g = (e & 31) << 2;
        float4 v = *(const float4*)&Qb[row * CI + g];
        split_store4(v, row * 136 + g, SQH, SQL);
    }

    // ldmatrix per-lane selectors
    const uint32_t sb = (uint32_t)__cvta_generic_to_shared(smem_bf);
    const int rowA = lane & 15;
    const int colA = ((lane >> 4) & 1) << 3;
    const int kRow = (((lane >> 4) & 1) << 3) | (lane & 7);
    const int kCol = ((lane >> 3) & 1) << 3;
    const int vRow = (((lane >> 3) & 1) << 3) | (lane & 7);
    const int vCol = ((lane >> 4) & 1) << 3;

    float o[2][16][4];
#pragma unroll
    for (int qt = 0; qt < 2; qt++)
#pragma unroll
        for (int t = 0; t < 16; t++)
#pragma unroll
            for (int j = 0; j < 4; j++) o[qt][t][j] = 0.f;
    float m_run[2][2], l_run[2][2];
#pragma unroll
    for (int qt = 0; qt < 2; qt++)
#pragma unroll
        for (int h = 0; h < 2; h++) { m_run[qt][h] = -3.0e38f; l_run[qt][h] = 0.f; }

    for (int kv0 = 0; kv0 < N2; kv0 += 64) {
        // ---- stage K and V (64 rows each), split hi/lo ----
#pragma unroll
        for (int i = 0; i < 8; i++) {
            int e = i * 256 + tid;
            int row = e >> 5;
            int g = (e & 31) << 2;
            int idx = row * 136 + g;
            float4 kv = *(const float4*)&Kb[(size_t)(kv0 + row) * CI + g];
            split_store4(kv, idx, SKH, SKL);
            float4 vv = *(const float4*)&Vb[(size_t)(kv0 + row) * CI + g];
            split_store4(vv, idx, SVH, SVL);
        }
        __syncthreads();

#pragma unroll
        for (int qt = 0; qt < 2; qt++) {
            // ---- S = Q K^T (16q x 64kv per warp) ----
            float sa[8][4];
#pragma unroll
            for (int t = 0; t < 8; t++)
#pragma unroll
                for (int j = 0; j < 4; j++) sa[t][j] = 0.f;

            const uint32_t aQ = sb + 2u * (SQH + (qt * 128 + warp * 16 + rowA) * 136 + colA);
#pragma unroll
            for (int kch = 0; kch < 8; kch++) {
                uint32_t qh[4], ql[4];
                ldsm4(qh, aQ + kch * 32);
                ldsm4(ql, aQ + kch * 32 + 2u * (SQL - SQH));
#pragma unroll
                for (int j = 0; j < 4; j++) {
                    uint32_t aK = sb + 2u * (SKH + ((j << 4) + kRow) * 136 + (kch << 4) + kCol);
                    uint32_t kh[4], kl[4];
                    ldsm4(kh, aK);
                    ldsm4(kl, aK + 2u * (SKL - SKH));
                    mma16816(sa[2 * j],     qh, kh[0], kh[1]);
                    mma16816(sa[2 * j],     qh, kl[0], kl[1]);
                    mma16816(sa[2 * j],     ql, kh[0], kh[1]);
                    mma16816(sa[2 * j + 1], qh, kh[2], kh[3]);
                    mma16816(sa[2 * j + 1], qh, kl[2], kl[3]);
                    mma16816(sa[2 * j + 1], ql, kh[2], kh[3]);
                }
            }

            // ---- online softmax (rows lane/4 and lane/4+8) ----
#pragma unroll
            for (int h = 0; h < 2; h++) {
                float mx = fmaxf(sa[0][2 * h], sa[0][2 * h + 1]);
#pragma unroll
                for (int t = 1; t < 8; t++)
                    mx = fmaxf(mx, fmaxf(sa[t][2 * h], sa[t][2 * h + 1]));
                mx = fmaxf(mx, __shfl_xor_sync(0xffffffffu, mx, 1));
                mx = fmaxf(mx, __shfl_xor_sync(0xffffffffu, mx, 2));
                float mnew = fmaxf(m_run[qt][h], mx);
                float al   = __expf(m_run[qt][h] - mnew);
                float rs = 0.f;
#pragma unroll
                for (int t = 0; t < 8; t++) {
                    sa[t][2 * h]     = __expf(sa[t][2 * h] - mnew);
                    sa[t][2 * h + 1] = __expf(sa[t][2 * h + 1] - mnew);
                    rs += sa[t][2 * h] + sa[t][2 * h + 1];
                }
                rs += __shfl_xor_sync(0xffffffffu, rs, 1);
                rs += __shfl_xor_sync(0xffffffffu, rs, 2);
                l_run[qt][h] = l_run[qt][h] * al + rs;
                m_run[qt][h] = mnew;
#pragma unroll
                for (int t = 0; t < 16; t++) {
                    o[qt][t][2 * h]     *= al;
                    o[qt][t][2 * h + 1] *= al;
                }
            }

            // ---- in-register P -> bf16 hi/lo A-fragments ----
            uint32_t ph[8][2], pl[8][2];
#pragma unroll
            for (int t = 0; t < 8; t++) {
                __nv_bfloat162 h01 = __floats2bfloat162_rn(sa[t][0], sa[t][1]);
                __nv_bfloat162 h23 = __floats2bfloat162_rn(sa[t][2], sa[t][3]);
                ph[t][0] = b2u(h01);
                ph[t][1] = b2u(h23);
                float r0 = sa[t][0] - __bfloat162float(h01.x);
                float r1 = sa[t][1] - __bfloat162float(h01.y);
                float r2 = sa[t][2] - __bfloat162float(h23.x);
                float r3 = sa[t][3] - __bfloat162float(h23.y);
                pl[t][0] = b2u(__floats2bfloat162_rn(r0, r1));
                pl[t][1] = b2u(__floats2bfloat162_rn(r2, r3));
            }

            // ---- O += P V (16q x 128ci per warp) ----
#pragma unroll
            for (int kch = 0; kch < 4; kch++) {
                uint32_t ah[4] = {ph[2 * kch][0], ph[2 * kch][1],
                                  ph[2 * kch + 1][0], ph[2 * kch + 1][1]};
                uint32_t al4[4] = {pl[2 * kch][0], pl[2 * kch][1],
                                   pl[2 * kch + 1][0], pl[2 * kch + 1][1]};
#pragma unroll
                for (int np = 0; np < 8; np++) {
                    uint32_t aV = sb + 2u * (SVH + ((kch << 4) + vRow) * 136 + (np << 4) + vCol);
                    uint32_t vh[4], vl[4];
                    ldsm4t(vh, aV);
                    ldsm4t(vl, aV + 2u * (SVL - SVH));
                    mma16816(o[qt][2 * np],     ah,  vh[0], vh[1]);
                    mma16816(o[qt][2 * np],     ah,  vl[0], vl[1]);
                    mma16816(o[qt][2 * np],     al4, vh[0], vh[1]);
                    mma16816(o[qt][2 * np + 1], ah,  vh[2], vh[3]);
                    mma16816(o[qt][2 * np + 1], ah,  vl[2], vl[3]);
                    mma16816(o[qt][2 * np + 1], al4, vh[2], vh[3]);
                }
            }
        }
        __syncthreads();
    }

    // ---- epilogue: normalize, write y fp32 [n][ci] ----
    float* Yb = g_buf + OFF_Y;
#pragma unroll
    for (int qt = 0; qt < 2; qt++) {
        float inv0 = 1.f / l_run[qt][0];
        float inv1 = 1.f / l_run[qt][1];
        int qr = q0 + qt * 128 + warp * 16 + (lane >> 2);
        float* y0 = Yb + ((size_t)b * NNq + qr) * CI + 2 * (lane & 3);
        float* y1 = Yb + ((size_t)b * NNq + qr + 8) * CI + 2 * (lane & 3);
#pragma unroll
        for (int t = 0; t < 16; t++) {
            float2 v0 = make_float2(o[qt][t][0] * inv0, o[qt][t][1] * inv0);
            float2 v1 = make_float2(o[qt][t][2] * inv1, o[qt][t][3] * inv1);
            *(float2*)&y0[8 * t] = v0;
            *(float2*)&y1[8 * t] = v1;
        }
    }
}

// ---------------------------------------------------------------------------
// Final (f32x2): out[b][co][n] = (sum_ci y[n][ci]*wf[co][ci] + bf - mean)*inv
//                + beta + x[b][co][n]
// ---------------------------------------------------------------------------
__global__ void __launch_bounds__(256)
final_kernel(const float* __restrict__ wf, const float* __restrict__ bf,
             const float* __restrict__ gamma, const float* __restrict__ beta,
             const float* __restrict__ mean, const float* __restrict__ var,
             const float* __restrict__ x, float* __restrict__ out)
{
    __shared__ __align__(16) float as[16][132];
    __shared__ __align__(16) float bs[16][132];

    const int b   = blockIdx.z;
    const int co0 = blockIdx.y * 128;
    const int n0  = blockIdx.x * 128;
    const int tid = threadIdx.x;
    const int txx = tid & 15;
    const int tyy = tid >> 4;

    ull acc[8][4];
#pragma unroll
    for (int i = 0; i < 8; i++)
#pragma unroll
        for (int j = 0; j < 4; j++) acc[i][j] = 0ULL;

    const float* yb = g_buf + OFF_Y + (size_t)b * NNq * CI;

    for (int k0 = 0; k0 < CI; k0 += 16) {
#pragma unroll
        for (int r = 0; r < 8; r++) {
            int e = r * 256 + tid;
            int co = e >> 4, k = e & 15;
            as[k][co] = wf[(co0 + co) * CI + k0 + k];
        }
#pragma unroll
        for (int r = 0; r < 8; r++) {
            int e = r * 256 + tid;
            int n = e >> 4, k = e & 15;
            bs[k][n] = yb[(size_t)(n0 + n) * CI + k0 + k];
        }
        __syncthreads();

#pragma unroll
        for (int k = 0; k < 16; k++) {
            float4 a0 = *(const float4*)&as[k][tyy * 4];
            float4 a1 = *(const float4*)&as[k][tyy * 4 + 64];
            ulonglong2 b0 = *(const ulonglong2*)&bs[k][txx * 4];
            ulonglong2 b1 = *(const ulonglong2*)&bs[k][txx * 4 + 64];
            float av[8] = {a0.x, a0.y, a0.z, a0.w, a1.x, a1.y, a1.z, a1.w};
#pragma unroll
            for (int i = 0; i < 8; i++) {
                ull d = dup2(av[i]);
                fma2(acc[i][0], d, b0.x);
                fma2(acc[i][1], d, b0.y);
                fma2(acc[i][2], d, b1.x);
                fma2(acc[i][3], d, b1.y);
            }
        }
        __syncthreads();
    }

#pragma unroll
    for (int i = 0; i < 8; i++) {
        int co = co0 + ((i < 4) ? (tyy * 4 + i) : (tyy * 4 + 64 + (i - 4)));
        float invs  = gamma[co] * rsqrtf(var[co] + BN_EPS);
        float shift = (bf[co] - mean[co]) * invs + beta[co];
        const float* xr = x + ((size_t)b * CC + co) * NNq + n0;
        float*      orw = out + ((size_t)b * CC + co) * NNq + n0;
        float f[8];
        unpk(acc[i][0], f[0], f[1]); unpk(acc[i][1], f[2], f[3]);
        unpk(acc[i][2], f[4], f[5]); unpk(acc[i][3], f[6], f[7]);
        float4 x0 = *(const float4*)&xr[txx * 4];
        float4 x1 = *(const float4*)&xr[txx * 4 + 64];
        float4 v0, v1;
        v0.x = f[0] * invs + shift + x0.x;
        v0.y = f[1] * invs + shift + x0.y;
        v0.z = f[2] * invs + shift + x0.z;
        v0.w = f[3] * invs + shift + x0.w;
        v1.x = f[4] * invs + shift + x1.x;
        v1.y = f[5] * invs + shift + x1.y;
        v1.z = f[6] * invs + shift + x1.z;
        v1.w = f[7] * invs + shift + x1.w;
        *(float4*)&orw[txx * 4]      = v0;
        *(float4*)&orw[txx * 4 + 64] = v1;
    }
}

// ---------------------------------------------------------------------------
extern "C" void kernel_launch(void* const* d_in, const int* in_sizes, int n_in,
                              void* d_out, int out_size)
{
    const float* x        = (const float*)d_in[0];
    const float* w_theta  = (const float*)d_in[1];
    const float* b_theta  = (const float*)d_in[2];
    const float* w_phi    = (const float*)d_in[3];
    const float* b_phi    = (const float*)d_in[4];
    const float* w_g      = (const float*)d_in[5];
    const float* b_g      = (const float*)d_in[6];
    const float* w_final  = (const float*)d_in[7];
    const float* b_final  = (const float*)d_in[8];
    const float* bn_gamma = (const float*)d_in[9];
    const float* bn_beta  = (const float*)d_in[10];
    const float* bn_mean  = (const float*)d_in[11];
    const float* bn_var   = (const float*)d_in[12];
    float* out = (float*)d_out;

    dim3 pgrid(NNq / 128, BB);
    proj_kernel<OFF_Q ><<<pgrid, 256>>>(x, w_theta, b_theta);
    proj_kernel<OFF_PF><<<pgrid, 256>>>(x, w_phi,   b_phi);
    proj_kernel<OFF_GF><<<pgrid, 256>>>(x, w_g,     b_g);

    pool_kernel<<<(BB * N2 * CI) / 256, 256>>>();

    static bool attn_attr_set = false;
    if (!attn_attr_set) {
        cudaFuncSetAttribute(attn_kernel,
                             cudaFuncAttributeMaxDynamicSharedMemorySize,
                             SM_BYTES);
        attn_attr_set = true;
    }
    dim3 agrid(NNq / 256, BB);
    attn_kernel<<<agrid, 256, SM_BYTES>>>();

    dim3 fgrid(NNq / 128, CC / 128, BB);
    final_kernel<<<fgrid, 256>>>(w_final, b_final, bn_gamma, bn_beta,
                                 bn_mean, bn_var, x, out);
}

// round 16
// speedup vs baseline: 1.0030x; 1.0030x over previous
#include <cuda_runtime.h>
#include <cuda_bf16.h>
#include <cstdint>
#include <cstddef>

// Problem constants
#define BB 4
#define CC 256
#define CI 128
#define NNq 8192      // T*H*W = 8*32*32
#define N2 2048       // T*16*16
#define BN_EPS 1e-5f

typedef unsigned long long ull;

// Scratch: single device-global buffer (no allocations allowed).
#define SZ_FULL (BB * NNq * CI)   // 4,194,304 floats
#define SZ_POOL (BB * N2 * CI)    // 1,048,576 floats
#define OFF_Q  0
#define OFF_PF (SZ_FULL)
#define OFF_GF (2 * SZ_FULL)
#define OFF_K  (3 * SZ_FULL)                 // [b][m][ci]
#define OFF_V  (3 * SZ_FULL + SZ_POOL)       // [b][m][ci]
#define OFF_Y  (3 * SZ_FULL + 2 * SZ_POOL)

__device__ __align__(16) float g_buf[3 * SZ_FULL + 2 * SZ_POOL + SZ_FULL];

// ---------------------------------------------------------------------------
// f32x2 packed-FMA helpers (for proj / final kernels)
// ---------------------------------------------------------------------------
__device__ __forceinline__ ull dup2(float a) {
    ull r; asm("mov.b64 %0, {%1, %1};" : "=l"(r) : "f"(a)); return r;
}
__device__ __forceinline__ void fma2(ull& d, ull a, ull b) {
    asm("fma.rn.f32x2 %0, %1, %2, %0;" : "+l"(d) : "l"(a), "l"(b));
}
__device__ __forceinline__ void unpk(ull v, float& lo, float& hi) {
    asm("mov.b64 {%0, %1}, %2;" : "=f"(lo), "=f"(hi) : "l"(v));
}

// ---------------------------------------------------------------------------
// mma.sync / ldmatrix helpers
// ---------------------------------------------------------------------------
__device__ __forceinline__ void ldsm4(uint32_t* r, uint32_t addr) {
    asm volatile("ldmatrix.sync.aligned.m8n8.x4.shared.b16 {%0,%1,%2,%3}, [%4];\n"
                 : "=r"(r[0]), "=r"(r[1]), "=r"(r[2]), "=r"(r[3]) : "r"(addr));
}
__device__ __forceinline__ void ldsm4t(uint32_t* r, uint32_t addr) {
    asm volatile("ldmatrix.sync.aligned.m8n8.x4.trans.shared.b16 {%0,%1,%2,%3}, [%4];\n"
                 : "=r"(r[0]), "=r"(r[1]), "=r"(r[2]), "=r"(r[3]) : "r"(addr));
}
__device__ __forceinline__ void mma16816(float* d, const uint32_t* a,
                                         uint32_t b0, uint32_t b1) {
    asm volatile(
        "mma.sync.aligned.m16n8k16.row.col.f32.bf16.bf16.f32 "
        "{%0,%1,%2,%3}, {%4,%5,%6,%7}, {%8,%9}, {%0,%1,%2,%3};\n"
        : "+f"(d[0]), "+f"(d[1]), "+f"(d[2]), "+f"(d[3])
        : "r"(a[0]), "r"(a[1]), "r"(a[2]), "r"(a[3]), "r"(b0), "r"(b1));
}
__device__ __forceinline__ uint32_t b2u(__nv_bfloat162 v) {
    return *reinterpret_cast<uint32_t*>(&v);
}

// ---------------------------------------------------------------------------
// Projection GEMM (f32x2): out[b][n][ci] = sum_c x[b][c][n]*w[ci][c] + bias
// ---------------------------------------------------------------------------
template <int OFF>
__global__ void __launch_bounds__(256)
proj_kernel(const float* __restrict__ x,
            const float* __restrict__ w,
            const float* __restrict__ bias)
{
    __shared__ __align__(16) float as[16][132];
    __shared__ __align__(16) float bs[16][132];

    const int b   = blockIdx.y;
    const int n0  = blockIdx.x * 128;
    const int tid = threadIdx.x;
    const int txx = tid & 15;
    const int tyy = tid >> 4;

    ull acc[8][4];
#pragma unroll
    for (int i = 0; i < 8; i++)
#pragma unroll
        for (int j = 0; j < 4; j++) acc[i][j] = 0ULL;

    const float* xb = x + (size_t)b * CC * NNq;

    for (int c0 = 0; c0 < CC; c0 += 16) {
#pragma unroll
        for (int r = 0; r < 8; r++) {
            int e = r * 256 + tid;
            int k = e >> 7, n = e & 127;
            as[k][n] = xb[(size_t)(c0 + k) * NNq + n0 + n];
        }
#pragma unroll
        for (int r = 0; r < 8; r++) {
            int e = r * 256 + tid;
            int ci = e >> 4, k = e & 15;
            bs[k][ci] = w[ci * CC + c0 + k];
        }
        __syncthreads();

#pragma unroll
        for (int k = 0; k < 16; k++) {
            float4 a0 = *(const float4*)&as[k][tyy * 4];
            float4 a1 = *(const float4*)&as[k][tyy * 4 + 64];
            ulonglong2 b0 = *(const ulonglong2*)&bs[k][txx * 4];
            ulonglong2 b1 = *(const ulonglong2*)&bs[k][txx * 4 + 64];
            float av[8] = {a0.x, a0.y, a0.z, a0.w, a1.x, a1.y, a1.z, a1.w};
#pragma unroll
            for (int i = 0; i < 8; i++) {
                ull d = dup2(av[i]);
                fma2(acc[i][0], d, b0.x);
                fma2(acc[i][1], d, b0.y);
                fma2(acc[i][2], d, b1.x);
                fma2(acc[i][3], d, b1.y);
            }
        }
        __syncthreads();
    }

    float bvv[8];
#pragma unroll
    for (int j = 0; j < 4; j++) {
        bvv[j]     = bias[txx * 4 + j];
        bvv[j + 4] = bias[txx * 4 + 64 + j];
    }
    float* out = g_buf + OFF;
#pragma unroll
    for (int i = 0; i < 8; i++) {
        int n = n0 + ((i < 4) ? (tyy * 4 + i) : (tyy * 4 + 64 + (i - 4)));
        float* o = out + (size_t)(b * NNq + n) * CI;
        float f[8];
        unpk(acc[i][0], f[0], f[1]); unpk(acc[i][1], f[2], f[3]);
        unpk(acc[i][2], f[4], f[5]); unpk(acc[i][3], f[6], f[7]);
        float4 v0, v1;
        v0.x = f[0] + bvv[0]; v0.y = f[1] + bvv[1];
        v0.z = f[2] + bvv[2]; v0.w = f[3] + bvv[3];
        v1.x = f[4] + bvv[4]; v1.y = f[5] + bvv[5];
        v1.z = f[6] + bvv[6]; v1.w = f[7] + bvv[7];
        *(float4*)&o[txx * 4]      = v0;
        *(float4*)&o[txx * 4 + 64] = v1;
    }
}

// ---------------------------------------------------------------------------
// 2x2 max pool: phi -> K [b][m][ci],  g -> V [b][m][ci]
// ---------------------------------------------------------------------------
__global__ void __launch_bounds__(256)
pool_kernel()
{
    int e = blockIdx.x * 256 + threadIdx.x;
    if (e >= BB * N2 * CI) return;
    int ci = e & 127;
    int r  = e >> 7;
    int m  = r & (N2 - 1);
    int b  = r >> 11;
    int t  = m >> 8;
    int h2 = (m >> 4) & 15;
    int w2 = m & 15;
    int nb = t * 1024 + (h2 * 2) * 32 + w2 * 2;
    size_t base = ((size_t)b * NNq + nb) * CI + ci;

    const float* pf = g_buf + OFF_PF;
    const float* gf = g_buf + OFF_GF;
    float p0 = pf[base], p1 = pf[base + CI], p2 = pf[base + 32 * CI], p3 = pf[base + 33 * CI];
    float q0 = gf[base], q1 = gf[base + CI], q2 = gf[base + 32 * CI], q3 = gf[base + 33 * CI];
    g_buf[OFF_K + e] = fmaxf(fmaxf(p0, p1), fmaxf(p2, p3));
    g_buf[OFF_V + e] = fmaxf(fmaxf(q0, q1), fmaxf(q2, q3));
}

// ---------------------------------------------------------------------------
// Tensor-core flash attention, bf16 3-MMA split precision.
// CTA: 256 threads (8 warps), 256 queries (2 tiles of 128), kv-blocks of 64.
// Warp w owns q rows [w*16, w*16+16) of each q-tile.
// smem (bf16, row stride 136): Qhi[256], Qlo[256], Khi/Klo[64], Vhi/Vlo[64].
// ---------------------------------------------------------------------------
#define SQH 0
#define SQL 34816            // 256*136
#define SKH 69632
#define SKL (69632 + 8704)   // 64*136
#define SVH (69632 + 17408)
#define SVL (69632 + 26112)
#define SM_ELEMS (69632 + 34816)
#define SM_BYTES (SM_ELEMS * 2)

extern __shared__ __align__(16) __nv_bfloat16 smem_bf[];

__device__ __forceinline__ void split_store4(float4 v, int idx, int hiOff, int loOff) {
    __nv_bfloat162 h01 = __floats2bfloat162_rn(v.x, v.y);
    __nv_bfloat162 h23 = __floats2bfloat162_rn(v.z, v.w);
    float r0 = v.x - __bfloat162float(h01.x);
    float r1 = v.y - __bfloat162float(h01.y);
    float r2 = v.z - __bfloat162float(h23.x);
    float r3 = v.w - __bfloat162float(h23.y);
    *(__nv_bfloat162*)&smem_bf[hiOff + idx]     = h01;
    *(__nv_bfloat162*)&smem_bf[hiOff + idx + 2] = h23;
    *(__nv_bfloat162*)&smem_bf[loOff + idx]     = __floats2bfloat162_rn(r0, r1);
    *(__nv_bfloat162*)&smem_bf[loOff + idx + 2] = __floats2bfloat162_rn(r2, r3);
}

__global__ void __launch_bounds__(256, 1)
attn_kernel()
{
    const int b    = blockIdx.y;
    const int q0   = blockIdx.x * 256;
    const int tid  = threadIdx.x;
    const int warp = tid >> 5;
    const int lane = tid & 31;

    const float* Qb = g_buf + OFF_Q + ((size_t)b * NNq + q0) * CI;
    const float* Kb = g_buf + OFF_K + (size_t)b * N2 * CI;
    const float* Vb = g_buf + OFF_V + (size_t)b * N2 * CI;

    // ---- stage Q (256 rows), split hi/lo ----
#pragma unroll 4
    for (int i = 0; i < 32; i++) {
        int e = i * 256 + tid;
        int row = e >> 5;
        int g = (e & 31) << 2;
        float4 v = *(const float4*)&Qb[row * CI + g];
        split_store4(v, row * 136 + g, SQH, SQL);
    }

    // ldmatrix per-lane selectors
    const uint32_t sb = (uint32_t)__cvta_generic_to_shared(smem_bf);
    const int rowA = lane & 15;
    const int colA = ((lane >> 4) & 1) << 3;
    const int kRow = (((lane >> 4) & 1) << 3) | (lane & 7);
    const int kCol = ((lane >> 3) & 1) << 3;
    const int vRow = (((lane >> 3) & 1) << 3) | (lane & 7);
    const int vCol = ((lane >> 4) & 1) << 3;

    float o[2][16][4];
#pragma unroll
    for (int qt = 0; qt < 2; qt++)
#pragma unroll
        for (int t = 0; t < 16; t++)
#pragma unroll
            for (int j = 0; j < 4; j++) o[qt][t][j] = 0.f;
    float m_run[2][2], l_run[2][2];
#pragma unroll
    for (int qt = 0; qt < 2; qt++)
#pragma unroll
        for (int h = 0; h < 2; h++) { m_run[qt][h] = -3.0e38f; l_run[qt][h] = 0.f; }

    for (int kv0 = 0; kv0 < N2; kv0 += 64) {
        // ---- stage K and V (64 rows each), split hi/lo ----
#pragma unroll
        for (int i = 0; i < 8; i++) {
            int e = i * 256 + tid;
            int row = e >> 5;
            int g = (e & 31) << 2;
            int idx = row * 136 + g;
            float4 kv = *(const float4*)&Kb[(size_t)(kv0 + row) * CI + g];
            split_store4(kv, idx, SKH, SKL);
            float4 vv = *(const float4*)&Vb[(size_t)(kv0 + row) * CI + g];
            split_store4(vv, idx, SVH, SVL);
        }
        __syncthreads();

#pragma unroll
        for (int qt = 0; qt < 2; qt++) {
            // ---- S = Q K^T (16q x 64kv per warp) ----
            float sa[8][4];
#pragma unroll
            for (int t = 0; t < 8; t++)
#pragma unroll
                for (int j = 0; j < 4; j++) sa[t][j] = 0.f;

            const uint32_t aQ = sb + 2u * (SQH + (qt * 128 + warp * 16 + rowA) * 136 + colA);
#pragma unroll
            for (int kch = 0; kch < 8; kch++) {
                uint32_t qh[4], ql[4];
                ldsm4(qh, aQ + kch * 32);
                ldsm4(ql, aQ + kch * 32 + 2u * (SQL - SQH));
#pragma unroll
                for (int j = 0; j < 4; j++) {
                    uint32_t aK = sb + 2u * (SKH + ((j << 4) + kRow) * 136 + (kch << 4) + kCol);
                    uint32_t kh[4], kl[4];
                    ldsm4(kh, aK);
                    ldsm4(kl, aK + 2u * (SKL - SKH));
                    mma16816(sa[2 * j],     qh, kh[0], kh[1]);
                    mma16816(sa[2 * j],     qh, kl[0], kl[1]);
                    mma16816(sa[2 * j],     ql, kh[0], kh[1]);
                    mma16816(sa[2 * j + 1], qh, kh[2], kh[3]);
                    mma16816(sa[2 * j + 1], qh, kl[2], kl[3]);
                    mma16816(sa[2 * j + 1], ql, kh[2], kh[3]);
                }
            }

            // ---- online softmax (rows lane/4 and lane/4+8) ----
#pragma unroll
            for (int h = 0; h < 2; h++) {
                float mx = fmaxf(sa[0][2 * h], sa[0][2 * h + 1]);
#pragma unroll
                for (int t = 1; t < 8; t++)
                    mx = fmaxf(mx, fmaxf(sa[t][2 * h], sa[t][2 * h + 1]));
                mx = fmaxf(mx, __shfl_xor_sync(0xffffffffu, mx, 1));
                mx = fmaxf(mx, __shfl_xor_sync(0xffffffffu, mx, 2));
                float mnew = fmaxf(m_run[qt][h], mx);
                float al   = __expf(m_run[qt][h] - mnew);
                float rs = 0.f;
#pragma unroll
                for (int t = 0; t < 8; t++) {
                    sa[t][2 * h]     = __expf(sa[t][2 * h] - mnew);
                    sa[t][2 * h + 1] = __expf(sa[t][2 * h + 1] - mnew);
                    rs += sa[t][2 * h] + sa[t][2 * h + 1];
                }
                rs += __shfl_xor_sync(0xffffffffu, rs, 1);
                rs += __shfl_xor_sync(0xffffffffu, rs, 2);
                l_run[qt][h] = l_run[qt][h] * al + rs;
                m_run[qt][h] = mnew;
#pragma unroll
                for (int t = 0; t < 16; t++) {
                    o[qt][t][2 * h]     *= al;
                    o[qt][t][2 * h + 1] *= al;
                }
            }

            // ---- in-register P -> bf16 hi/lo A-fragments ----
            uint32_t ph[8][2], pl[8][2];
#pragma unroll
            for (int t = 0; t < 8; t++) {
                __nv_bfloat162 h01 = __floats2bfloat162_rn(sa[t][0], sa[t][1]);
                __nv_bfloat162 h23 = __floats2bfloat162_rn(sa[t][2], sa[t][3]);
                ph[t][0] = b2u(h01);
                ph[t][1] = b2u(h23);
                float r0 = sa[t][0] - __bfloat162float(h01.x);
                float r1 = sa[t][1] - __bfloat162float(h01.y);
                float r2 = sa[t][2] - __bfloat162float(h23.x);
                float r3 = sa[t][3] - __bfloat162float(h23.y);
                pl[t][0] = b2u(__floats2bfloat162_rn(r0, r1));
                pl[t][1] = b2u(__floats2bfloat162_rn(r2, r3));
            }

            // ---- O += P V (16q x 128ci per warp) ----
#pragma unroll
            for (int kch = 0; kch < 4; kch++) {
                uint32_t ah[4] = {ph[2 * kch][0], ph[2 * kch][1],
                                  ph[2 * kch + 1][0], ph[2 * kch + 1][1]};
                uint32_t al4[4] = {pl[2 * kch][0], pl[2 * kch][1],
                                   pl[2 * kch + 1][0], pl[2 * kch + 1][1]};
#pragma unroll
                for (int np = 0; np < 8; np++) {
                    uint32_t aV = sb + 2u * (SVH + ((kch << 4) + vRow) * 136 + (np << 4) + vCol);
                    uint32_t vh[4], vl[4];
                    ldsm4t(vh, aV);
                    ldsm4t(vl, aV + 2u * (SVL - SVH));
                    mma16816(o[qt][2 * np],     ah,  vh[0], vh[1]);
                    mma16816(o[qt][2 * np],     ah,  vl[0], vl[1]);
                    mma16816(o[qt][2 * np],     al4, vh[0], vh[1]);
                    mma16816(o[qt][2 * np + 1], ah,  vh[2], vh[3]);
                    mma16816(o[qt][2 * np + 1], ah,  vl[2], vl[3]);
                    mma16816(o[qt][2 * np + 1], al4, vh[2], vh[3]);
                }
            }
        }
        __syncthreads();
    }

    // ---- epilogue: normalize, write y fp32 [n][ci] ----
    float* Yb = g_buf + OFF_Y;
#pragma unroll
    for (int qt = 0; qt < 2; qt++) {
        float inv0 = 1.f / l_run[qt][0];
        float inv1 = 1.f / l_run[qt][1];
        int qr = q0 + qt * 128 + warp * 16 + (lane >> 2);
        float* y0 = Yb + ((size_t)b * NNq + qr) * CI + 2 * (lane & 3);
        float* y1 = Yb + ((size_t)b * NNq + qr + 8) * CI + 2 * (lane & 3);
#pragma unroll
        for (int t = 0; t < 16; t++) {
            float2 v0 = make_float2(o[qt][t][0] * inv0, o[qt][t][1] * inv0);
            float2 v1 = make_float2(o[qt][t][2] * inv1, o[qt][t][3] * inv1);
            *(float2*)&y0[8 * t] = v0;
            *(float2*)&y1[8 * t] = v1;
        }
    }
}

// ---------------------------------------------------------------------------
// Final (f32x2): out[b][co][n] = (sum_ci y[n][ci]*wf[co][ci] + bf - mean)*inv
//                + beta + x[b][co][n]
// ---------------------------------------------------------------------------
__global__ void __launch_bounds__(256)
final_kernel(const float* __restrict__ wf, const float* __restrict__ bf,
             const float* __restrict__ gamma, const float* __restrict__ beta,
             const float* __restrict__ mean, const float* __restrict__ var,
             const float* __restrict__ x, float* __restrict__ out)
{
    __shared__ __align__(16) float as[16][132];
    __shared__ __align__(16) float bs[16][132];

    const int b   = blockIdx.z;
    const int co0 = blockIdx.y * 128;
    const int n0  = blockIdx.x * 128;
    const int tid = threadIdx.x;
    const int txx = tid & 15;
    const int tyy = tid >> 4;

    ull acc[8][4];
#pragma unroll
    for (int i = 0; i < 8; i++)
#pragma unroll
        for (int j = 0; j < 4; j++) acc[i][j] = 0ULL;

    const float* yb = g_buf + OFF_Y + (size_t)b * NNq * CI;

    for (int k0 = 0; k0 < CI; k0 += 16) {
#pragma unroll
        for (int r = 0; r < 8; r++) {
            int e = r * 256 + tid;
            int co = e >> 4, k = e & 15;
            as[k][co] = wf[(co0 + co) * CI + k0 + k];
        }
#pragma unroll
        for (int r = 0; r < 8; r++) {
            int e = r * 256 + tid;
            int n = e >> 4, k = e & 15;
            bs[k][n] = yb[(size_t)(n0 + n) * CI + k0 + k];
        }
        __syncthreads();

#pragma unroll
        for (int k = 0; k < 16; k++) {
            float4 a0 = *(const float4*)&as[k][tyy * 4];
            float4 a1 = *(const float4*)&as[k][tyy * 4 + 64];
            ulonglong2 b0 = *(const ulonglong2*)&bs[k][txx * 4];
            ulonglong2 b1 = *(const ulonglong2*)&bs[k][txx * 4 + 64];
            float av[8] = {a0.x, a0.y, a0.z, a0.w, a1.x, a1.y, a1.z, a1.w};
#pragma unroll
            for (int i = 0; i < 8; i++) {
                ull d = dup2(av[i]);
                fma2(acc[i][0], d, b0.x);
                fma2(acc[i][1], d, b0.y);
                fma2(acc[i][2], d, b1.x);
                fma2(acc[i][3], d, b1.y);
            }
        }
        __syncthreads();
    }

#pragma unroll
    for (int i = 0; i < 8; i++) {
        int co = co0 + ((i < 4) ? (tyy * 4 + i) : (tyy * 4 + 64 + (i - 4)));
        float invs  = gamma[co] * rsqrtf(var[co] + BN_EPS);
        float shift = (bf[co] - mean[co]) * invs + beta[co];
        const float* xr = x + ((size_t)b * CC + co) * NNq + n0;
        float*      orw = out + ((size_t)b * CC + co) * NNq + n0;
        float f[8];
        unpk(acc[i][0], f[0], f[1]); unpk(acc[i][1], f[2], f[3]);
        unpk(acc[i][2], f[4], f[5]); unpk(acc[i][3], f[6], f[7]);
        float4 x0 = *(const float4*)&xr[txx * 4];
        float4 x1 = *(const float4*)&xr[txx * 4 + 64];
        float4 v0, v1;
        v0.x = f[0] * invs + shift + x0.x;
        v0.y = f[1] * invs + shift + x0.y;
        v0.z = f[2] * invs + shift + x0.z;
        v0.w = f[3] * invs + shift + x0.w;
        v1.x = f[4] * invs + shift + x1.x;
        v1.y = f[5] * invs + shift + x1.y;
        v1.z = f[6] * invs + shift + x1.z;
        v1.w = f[7] * invs + shift + x1.w;
        *(float4*)&orw[txx * 4]      = v0;
        *(float4*)&orw[txx * 4 + 64] = v1;
    }
}

// ---------------------------------------------------------------------------
extern "C" void kernel_launch(void* const* d_in, const int* in_sizes, int n_in,
                              void* d_out, int out_size)
{
    const float* x        = (const float*)d_in[0];
    const float* w_theta  = (const float*)d_in[1];
    const float* b_theta  = (const float*)d_in[2];
    const float* w_phi    = (const float*)d_in[3];
    const float* b_phi    = (const float*)d_in[4];
    const float* w_g      = (const float*)d_in[5];
    const float* b_g      = (const float*)d_in[6];
    const float* w_final  = (const float*)d_in[7];
    const float* b_final  = (const float*)d_in[8];
    const float* bn_gamma = (const float*)d_in[9];
    const float* bn_beta  = (const float*)d_in[10];
    const float* bn_mean  = (const float*)d_in[11];
    const float* bn_var   = (const float*)d_in[12];
    float* out = (float*)d_out;

    dim3 pgrid(NNq / 128, BB);
    proj_kernel<OFF_Q ><<<pgrid, 256>>>(x, w_theta, b_theta);
    proj_kernel<OFF_PF><<<pgrid, 256>>>(x, w_phi,   b_phi);
    proj_kernel<OFF_GF><<<pgrid, 256>>>(x, w_g,     b_g);

    pool_kernel<<<(BB * N2 * CI) / 256, 256>>>();

    static bool attn_attr_set = false;
    if (!attn_attr_set) {
        cudaFuncSetAttribute(attn_kernel,
                             cudaFuncAttributeMaxDynamicSharedMemorySize,
                             SM_BYTES);
        attn_attr_set = true;
    }
    dim3 agrid(NNq / 256, BB);
    attn_kernel<<<agrid, 256, SM_BYTES>>>();

    dim3 fgrid(NNq / 128, CC / 128, BB);
    final_kernel<<<fgrid, 256>>>(w_final, b_final, bn_gamma, bn_beta,
                                 bn_mean, bn_var, x, out);
}

// round 17
// speedup vs baseline: 1.0031x; 1.0001x over previous
#include <cuda_runtime.h>
#include <cuda_bf16.h>
#include <cstdint>
#include <cstddef>

// Problem constants
#define BB 4
#define CC 256
#define CI 128
#define NNq 8192      // T*H*W = 8*32*32
#define N2 2048       // T*16*16
#define BN_EPS 1e-5f

typedef unsigned long long ull;

// Scratch: single device-global buffer (no allocations allowed).
#define SZ_FULL (BB * NNq * CI)   // 4,194,304 floats
#define SZ_POOL (BB * N2 * CI)    // 1,048,576 floats
#define OFF_Q  0
#define OFF_PF (SZ_FULL)
#define OFF_GF (2 * SZ_FULL)
#define OFF_K  (3 * SZ_FULL)                 // [b][m][ci]
#define OFF_V  (3 * SZ_FULL + SZ_POOL)       // [b][m][ci]
#define OFF_Y  (3 * SZ_FULL + 2 * SZ_POOL)

__device__ __align__(16) float g_buf[3 * SZ_FULL + 2 * SZ_POOL + SZ_FULL];

// ---------------------------------------------------------------------------
// f32x2 packed-FMA helpers (for proj / final kernels)
// ---------------------------------------------------------------------------
__device__ __forceinline__ ull dup2(float a) {
    ull r; asm("mov.b64 %0, {%1, %1};" : "=l"(r) : "f"(a)); return r;
}
__device__ __forceinline__ void fma2(ull& d, ull a, ull b) {
    asm("fma.rn.f32x2 %0, %1, %2, %0;" : "+l"(d) : "l"(a), "l"(b));
}
__device__ __forceinline__ void unpk(ull v, float& lo, float& hi) {
    asm("mov.b64 {%0, %1}, %2;" : "=f"(lo), "=f"(hi) : "l"(v));
}

// ---------------------------------------------------------------------------
// mma.sync / ldmatrix helpers
// ---------------------------------------------------------------------------
__device__ __forceinline__ void ldsm4(uint32_t* r, uint32_t addr) {
    asm volatile("ldmatrix.sync.aligned.m8n8.x4.shared.b16 {%0,%1,%2,%3}, [%4];\n"
                 : "=r"(r[0]), "=r"(r[1]), "=r"(r[2]), "=r"(r[3]) : "r"(addr));
}
__device__ __forceinline__ void ldsm4t(uint32_t* r, uint32_t addr) {
    asm volatile("ldmatrix.sync.aligned.m8n8.x4.trans.shared.b16 {%0,%1,%2,%3}, [%4];\n"
                 : "=r"(r[0]), "=r"(r[1]), "=r"(r[2]), "=r"(r[3]) : "r"(addr));
}
__device__ __forceinline__ void mma16816(float* d, const uint32_t* a,
                                         uint32_t b0, uint32_t b1) {
    asm volatile(
        "mma.sync.aligned.m16n8k16.row.col.f32.bf16.bf16.f32 "
        "{%0,%1,%2,%3}, {%4,%5,%6,%7}, {%8,%9}, {%0,%1,%2,%3};\n"
        : "+f"(d[0]), "+f"(d[1]), "+f"(d[2]), "+f"(d[3])
        : "r"(a[0]), "r"(a[1]), "r"(a[2]), "r"(a[3]), "r"(b0), "r"(b1));
}
__device__ __forceinline__ uint32_t b2u(__nv_bfloat162 v) {
    return *reinterpret_cast<uint32_t*>(&v);
}

// ---------------------------------------------------------------------------
// Projection GEMM (f32x2): out[b][n][ci] = sum_c x[b][c][n]*w[ci][c] + bias
// ---------------------------------------------------------------------------
template <int OFF>
__global__ void __launch_bounds__(256)
proj_kernel(const float* __restrict__ x,
            const float* __restrict__ w,
            const float* __restrict__ bias)
{
    __shared__ __align__(16) float as[16][132];
    __shared__ __align__(16) float bs[16][132];

    const int b   = blockIdx.y;
    const int n0  = blockIdx.x * 128;
    const int tid = threadIdx.x;
    const int txx = tid & 15;
    const int tyy = tid >> 4;

    ull acc[8][4];
#pragma unroll
    for (int i = 0; i < 8; i++)
#pragma unroll
        for (int j = 0; j < 4; j++) acc[i][j] = 0ULL;

    const float* xb = x + (size_t)b * CC * NNq;

    for (int c0 = 0; c0 < CC; c0 += 16) {
#pragma unroll
        for (int r = 0; r < 8; r++) {
            int e = r * 256 + tid;
            int k = e >> 7, n = e & 127;
            as[k][n] = xb[(size_t)(c0 + k) * NNq + n0 + n];
        }
#pragma unroll
        for (int r = 0; r < 8; r++) {
            int e = r * 256 + tid;
            int ci = e >> 4, k = e & 15;
            bs[k][ci] = w[ci * CC + c0 + k];
        }
        __syncthreads();

#pragma unroll
        for (int k = 0; k < 16; k++) {
            float4 a0 = *(const float4*)&as[k][tyy * 4];
            float4 a1 = *(const float4*)&as[k][tyy * 4 + 64];
            ulonglong2 b0 = *(const ulonglong2*)&bs[k][txx * 4];
            ulonglong2 b1 = *(const ulonglong2*)&bs[k][txx * 4 + 64];
            float av[8] = {a0.x, a0.y, a0.z, a0.w, a1.x, a1.y, a1.z, a1.w};
#pragma unroll
            for (int i = 0; i < 8; i++) {
                ull d = dup2(av[i]);
                fma2(acc[i][0], d, b0.x);
                fma2(acc[i][1], d, b0.y);
                fma2(acc[i][2], d, b1.x);
                fma2(acc[i][3], d, b1.y);
            }
        }
        __syncthreads();
    }

    float bvv[8];
#pragma unroll
    for (int j = 0; j < 4; j++) {
        bvv[j]     = bias[txx * 4 + j];
        bvv[j + 4] = bias[txx * 4 + 64 + j];
    }
    float* out = g_buf + OFF;
#pragma unroll
    for (int i = 0; i < 8; i++) {
        int n = n0 + ((i < 4) ? (tyy * 4 + i) : (tyy * 4 + 64 + (i - 4)));
        float* o = out + (size_t)(b * NNq + n) * CI;
        float f[8];
        unpk(acc[i][0], f[0], f[1]); unpk(acc[i][1], f[2], f[3]);
        unpk(acc[i][2], f[4], f[5]); unpk(acc[i][3], f[6], f[7]);
        float4 v0, v1;
        v0.x = f[0] + bvv[0]; v0.y = f[1] + bvv[1];
        v0.z = f[2] + bvv[2]; v0.w = f[3] + bvv[3];
        v1.x = f[4] + bvv[4]; v1.y = f[5] + bvv[5];
        v1.z = f[6] + bvv[6]; v1.w = f[7] + bvv[7];
        *(float4*)&o[txx * 4]      = v0;
        *(float4*)&o[txx * 4 + 64] = v1;
    }
}

// ---------------------------------------------------------------------------
// 2x2 max pool: phi -> K [b][m][ci],  g -> V [b][m][ci]
// ---------------------------------------------------------------------------
__global__ void __launch_bounds__(256)
pool_kernel()
{
    int e = blockIdx.x * 256 + threadIdx.x;
    if (e >= BB * N2 * CI) return;
    int ci = e & 127;
    int r  = e >> 7;
    int m  = r & (N2 - 1);
    int b  = r >> 11;
    int t  = m >> 8;
    int h2 = (m >> 4) & 15;
    int w2 = m & 15;
    int nb = t * 1024 + (h2 * 2) * 32 + w2 * 2;
    size_t base = ((size_t)b * NNq + nb) * CI + ci;

    const float* pf = g_buf + OFF_PF;
    const float* gf = g_buf + OFF_GF;
    float p0 = pf[base], p1 = pf[base + CI], p2 = pf[base + 32 * CI], p3 = pf[base + 33 * CI];
    float q0 = gf[base], q1 = gf[base + CI], q2 = gf[base + 32 * CI], q3 = gf[base + 33 * CI];
    g_buf[OFF_K + e] = fmaxf(fmaxf(p0, p1), fmaxf(p2, p3));
    g_buf[OFF_V + e] = fmaxf(fmaxf(q0, q1), fmaxf(q2, q3));
}

// ---------------------------------------------------------------------------
// Tensor-core flash attention, bf16 3-MMA split precision.
// CTA: 256 threads (8 warps), 256 queries (2 tiles of 128), kv-blocks of 64.
// Warp w owns q rows [w*16, w*16+16) of each q-tile.
// smem (bf16, row stride 136): Qhi[256], Qlo[256], Khi/Klo[64], Vhi/Vlo[64].
// ---------------------------------------------------------------------------
#define SQH 0
#define SQL 34816            // 256*136
#define SKH 69632
#define SKL (69632 + 8704)   // 64*136
#define SVH (69632 + 17408)
#define SVL (69632 + 26112)
#define SM_ELEMS (69632 + 34816)
#define SM_BYTES (SM_ELEMS * 2)

extern __shared__ __align__(16) __nv_bfloat16 smem_bf[];

__device__ __forceinline__ void split_store4(float4 v, int idx, int hiOff, int loOff) {
    __nv_bfloat162 h01 = __floats2bfloat162_rn(v.x, v.y);
    __nv_bfloat162 h23 = __floats2bfloat162_rn(v.z, v.w);
    float r0 = v.x - __bfloat162float(h01.x);
    float r1 = v.y - __bfloat162float(h01.y);
    float r2 = v.z - __bfloat162float(h23.x);
    float r3 = v.w - __bfloat162float(h23.y);
    *(__nv_bfloat162*)&smem_bf[hiOff + idx]     = h01;
    *(__nv_bfloat162*)&smem_bf[hiOff + idx + 2] = h23;
    *(__nv_bfloat162*)&smem_bf[loOff + idx]     = __floats2bfloat162_rn(r0, r1);
    *(__nv_bfloat162*)&smem_bf[loOff + idx + 2] = __floats2bfloat162_rn(r2, r3);
}

__global__ void __launch_bounds__(256, 1)
attn_kernel()
{
    const int b    = blockIdx.y;
    const int q0   = blockIdx.x * 256;
    const int tid  = threadIdx.x;
    const int warp = tid >> 5;
    const int lane = tid & 31;

    const float* Qb = g_buf + OFF_Q + ((size_t)b * NNq + q0) * CI;
    const float* Kb = g_buf + OFF_K + (size_t)b * N2 * CI;
    const float* Vb = g_buf + OFF_V + (size_t)b * N2 * CI;

    // ---- stage Q (256 rows), split hi/lo ----
#pragma unroll 4
    for (int i = 0; i < 32; i++) {
        int e = i * 256 + tid;
        int row = e >> 5;
        int g = (e & 31) << 2;
        float4 v = *(const float4*)&Qb[row * CI + g];
        split_store4(v, row * 136 + g, SQH, SQL);
    }

    // ldmatrix per-lane selectors
    const uint32_t sb = (uint32_t)__cvta_generic_to_shared(smem_bf);
    const int rowA = lane & 15;
    const int colA = ((lane >> 4) & 1) << 3;
    const int kRow = (((lane >> 4) & 1) << 3) | (lane & 7);
    const int kCol = ((lane >> 3) & 1) << 3;
    const int vRow = (((lane >> 3) & 1) << 3) | (lane & 7);
    const int vCol = ((lane >> 4) & 1) << 3;

    float o[2][16][4];
#pragma unroll
    for (int qt = 0; qt < 2; qt++)
#pragma unroll
        for (int t = 0; t < 16; t++)
#pragma unroll
            for (int j = 0; j < 4; j++) o[qt][t][j] = 0.f;
    float m_run[2][2], l_run[2][2];
#pragma unroll
    for (int qt = 0; qt < 2; qt++)
#pragma unroll
        for (int h = 0; h < 2; h++) { m_run[qt][h] = -3.0e38f; l_run[qt][h] = 0.f; }

    for (int kv0 = 0; kv0 < N2; kv0 += 64) {
        // ---- stage K and V (64 rows each), split hi/lo ----
#pragma unroll
        for (int i = 0; i < 8; i++) {
            int e = i * 256 + tid;
            int row = e >> 5;
            int g = (e & 31) << 2;
            int idx = row * 136 + g;
            float4 kv = *(const float4*)&Kb[(size_t)(kv0 + row) * CI + g];
            split_store4(kv, idx, SKH, SKL);
            float4 vv = *(const float4*)&Vb[(size_t)(kv0 + row) * CI + g];
            split_store4(vv, idx, SVH, SVL);
        }
        __syncthreads();

#pragma unroll
        for (int qt = 0; qt < 2; qt++) {
            // ---- S = Q K^T (16q x 64kv per warp) ----
            float sa[8][4];
#pragma unroll
            for (int t = 0; t < 8; t++)
#pragma unroll
                for (int j = 0; j < 4; j++) sa[t][j] = 0.f;

            const uint32_t aQ = sb + 2u * (SQH + (qt * 128 + warp * 16 + rowA) * 136 + colA);
#pragma unroll
            for (int kch = 0; kch < 8; kch++) {
                uint32_t qh[4], ql[4];
                ldsm4(qh, aQ + kch * 32);
                ldsm4(ql, aQ + kch * 32 + 2u * (SQL - SQH));
#pragma unroll
                for (int j = 0; j < 4; j++) {
                    uint32_t aK = sb + 2u * (SKH + ((j << 4) + kRow) * 136 + (kch << 4) + kCol);
                    uint32_t kh[4], kl[4];
                    ldsm4(kh, aK);
                    ldsm4(kl, aK + 2u * (SKL - SKH));
                    mma16816(sa[2 * j],     qh, kh[0], kh[1]);
                    mma16816(sa[2 * j],     qh, kl[0], kl[1]);
                    mma16816(sa[2 * j],     ql, kh[0], kh[1]);
                    mma16816(sa[2 * j + 1], qh, kh[2], kh[3]);
                    mma16816(sa[2 * j + 1], qh, kl[2], kl[3]);
                    mma16816(sa[2 * j + 1], ql, kh[2], kh[3]);
                }
            }

            // ---- online softmax (rows lane/4 and lane/4+8) ----
#pragma unroll
            for (int h = 0; h < 2; h++) {
                float mx = fmaxf(sa[0][2 * h], sa[0][2 * h + 1]);
#pragma unroll
                for (int t = 1; t < 8; t++)
                    mx = fmaxf(mx, fmaxf(sa[t][2 * h], sa[t][2 * h + 1]));
                mx = fmaxf(mx, __shfl_xor_sync(0xffffffffu, mx, 1));
                mx = fmaxf(mx, __shfl_xor_sync(0xffffffffu, mx, 2));
                float mnew = fmaxf(m_run[qt][h], mx);
                float al   = __expf(m_run[qt][h] - mnew);
                float rs = 0.f;
#pragma unroll
                for (int t = 0; t < 8; t++) {
                    sa[t][2 * h]     = __expf(sa[t][2 * h] - mnew);
                    sa[t][2 * h + 1] = __expf(sa[t][2 * h + 1] - mnew);
                    rs += sa[t][2 * h] + sa[t][2 * h + 1];
                }
                rs += __shfl_xor_sync(0xffffffffu, rs, 1);
                rs += __shfl_xor_sync(0xffffffffu, rs, 2);
                l_run[qt][h] = l_run[qt][h] * al + rs;
                m_run[qt][h] = mnew;
#pragma unroll
                for (int t = 0; t < 16; t++) {
                    o[qt][t][2 * h]     *= al;
                    o[qt][t][2 * h + 1] *= al;
                }
            }

            // ---- in-register P -> bf16 hi/lo A-fragments ----
            uint32_t ph[8][2], pl[8][2];
#pragma unroll
            for (int t = 0; t < 8; t++) {
                __nv_bfloat162 h01 = __floats2bfloat162_rn(sa[t][0], sa[t][1]);
                __nv_bfloat162 h23 = __floats2bfloat162_rn(sa[t][2], sa[t][3]);
                ph[t][0] = b2u(h01);
                ph[t][1] = b2u(h23);
                float r0 = sa[t][0] - __bfloat162float(h01.x);
                float r1 = sa[t][1] - __bfloat162float(h01.y);
                float r2 = sa[t][2] - __bfloat162float(h23.x);
                float r3 = sa[t][3] - __bfloat162float(h23.y);
                pl[t][0] = b2u(__floats2bfloat162_rn(r0, r1));
                pl[t][1] = b2u(__floats2bfloat162_rn(r2, r3));
            }

            // ---- O += P V (16q x 128ci per warp) ----
#pragma unroll
            for (int kch = 0; kch < 4; kch++) {
                uint32_t ah[4] = {ph[2 * kch][0], ph[2 * kch][1],
                                  ph[2 * kch + 1][0], ph[2 * kch + 1][1]};
                uint32_t al4[4] = {pl[2 * kch][0], pl[2 * kch][1],
                                   pl[2 * kch + 1][0], pl[2 * kch + 1][1]};
#pragma unroll
                for (int np = 0; np < 8; np++) {
                    uint32_t aV = sb + 2u * (SVH + ((kch << 4) + vRow) * 136 + (np << 4) + vCol);
                    uint32_t vh[4], vl[4];
                    ldsm4t(vh, aV);
                    ldsm4t(vl, aV + 2u * (SVL - SVH));
                    mma16816(o[qt][2 * np],     ah,  vh[0], vh[1]);
                    mma16816(o[qt][2 * np],     ah,  vl[0], vl[1]);
                    mma16816(o[qt][2 * np],     al4, vh[0], vh[1]);
                    mma16816(o[qt][2 * np + 1], ah,  vh[2], vh[3]);
                    mma16816(o[qt][2 * np + 1], ah,  vl[2], vl[3]);
                    mma16816(o[qt][2 * np + 1], al4, vh[2], vh[3]);
                }
            }
        }
        __syncthreads();
    }

    // ---- epilogue: normalize, write y fp32 [n][ci] ----
    float* Yb = g_buf + OFF_Y;
#pragma unroll
    for (int qt = 0; qt < 2; qt++) {
        float inv0 = 1.f / l_run[qt][0];
        float inv1 = 1.f / l_run[qt][1];
        int qr = q0 + qt * 128 + warp * 16 + (lane >> 2);
        float* y0 = Yb + ((size_t)b * NNq + qr) * CI + 2 * (lane & 3);
        float* y1 = Yb + ((size_t)b * NNq + qr + 8) * CI + 2 * (lane & 3);
#pragma unroll
        for (int t = 0; t < 16; t++) {
            float2 v0 = make_float2(o[qt][t][0] * inv0, o[qt][t][1] * inv0);
            float2 v1 = make_float2(o[qt][t][2] * inv1, o[qt][t][3] * inv1);
            *(float2*)&y0[8 * t] = v0;
            *(float2*)&y1[8 * t] = v1;
        }
    }
}

// ---------------------------------------------------------------------------
// Final (f32x2): out[b][co][n] = (sum_ci y[n][ci]*wf[co][ci] + bf - mean)*inv
//                + beta + x[b][co][n]
// ---------------------------------------------------------------------------
__global__ void __launch_bounds__(256)
final_kernel(const float* __restrict__ wf, const float* __restrict__ bf,
             const float* __restrict__ gamma, const float* __restrict__ beta,
             const float* __restrict__ mean, const float* __restrict__ var,
             const float* __restrict__ x, float* __restrict__ out)
{
    __shared__ __align__(16) float as[16][132];
    __shared__ __align__(16) float bs[16][132];

    const int b   = blockIdx.z;
    const int co0 = blockIdx.y * 128;
    const int n0  = blockIdx.x * 128;
    const int tid = threadIdx.x;
    const int txx = tid & 15;
    const int tyy = tid >> 4;

    ull acc[8][4];
#pragma unroll
    for (int i = 0; i < 8; i++)
#pragma unroll
        for (int j = 0; j < 4; j++) acc[i][j] = 0ULL;

    const float* yb = g_buf + OFF_Y + (size_t)b * NNq * CI;

    for (int k0 = 0; k0 < CI; k0 += 16) {
#pragma unroll
        for (int r = 0; r < 8; r++) {
            int e = r * 256 + tid;
            int co = e >> 4, k = e & 15;
            as[k][co] = wf[(co0 + co) * CI + k0 + k];
        }
#pragma unroll
        for (int r = 0; r < 8; r++) {
            int e = r * 256 + tid;
            int n = e >> 4, k = e & 15;
            bs[k][n] = yb[(size_t)(n0 + n) * CI + k0 + k];
        }
        __syncthreads();

#pragma unroll
        for (int k = 0; k < 16; k++) {
            float4 a0 = *(const float4*)&as[k][tyy * 4];
            float4 a1 = *(const float4*)&as[k][tyy * 4 + 64];
            ulonglong2 b0 = *(const ulonglong2*)&bs[k][txx * 4];
            ulonglong2 b1 = *(const ulonglong2*)&bs[k][txx * 4 + 64];
            float av[8] = {a0.x, a0.y, a0.z, a0.w, a1.x, a1.y, a1.z, a1.w};
#pragma unroll
            for (int i = 0; i < 8; i++) {
                ull d = dup2(av[i]);
                fma2(acc[i][0], d, b0.x);
                fma2(acc[i][1], d, b0.y);
                fma2(acc[i][2], d, b1.x);
                fma2(acc[i][3], d, b1.y);
            }
        }
        __syncthreads();
    }

#pragma unroll
    for (int i = 0; i < 8; i++) {
        int co = co0 + ((i < 4) ? (tyy * 4 + i) : (tyy * 4 + 64 + (i - 4)));
        float invs  = gamma[co] * rsqrtf(var[co] + BN_EPS);
        float shift = (bf[co] - mean[co]) * invs + beta[co];
        const float* xr = x + ((size_t)b * CC + co) * NNq + n0;
        float*      orw = out + ((size_t)b * CC + co) * NNq + n0;
        float f[8];
        unpk(acc[i][0], f[0], f[1]); unpk(acc[i][1], f[2], f[3]);
        unpk(acc[i][2], f[4], f[5]); unpk(acc[i][3], f[6], f[7]);
        float4 x0 = *(const float4*)&xr[txx * 4];
        float4 x1 = *(const float4*)&xr[txx * 4 + 64];
        float4 v0, v1;
        v0.x = f[0] * invs + shift + x0.x;
        v0.y = f[1] * invs + shift + x0.y;
        v0.z = f[2] * invs + shift + x0.z;
        v0.w = f[3] * invs + shift + x0.w;
        v1.x = f[4] * invs + shift + x1.x;
        v1.y = f[5] * invs + shift + x1.y;
        v1.z = f[6] * invs + shift + x1.z;
        v1.w = f[7] * invs + shift + x1.w;
        *(float4*)&orw[txx * 4]      = v0;
        *(float4*)&orw[txx * 4 + 64] = v1;
    }
}

// ---------------------------------------------------------------------------
extern "C" void kernel_launch(void* const* d_in, const int* in_sizes, int n_in,
                              void* d_out, int out_size)
{
    const float* x        = (const float*)d_in[0];
    const float* w_theta  = (const float*)d_in[1];
    const float* b_theta  = (const float*)d_in[2];
    const float* w_phi    = (const float*)d_in[3];
    const float* b_phi    = (const float*)d_in[4];
    const float* w_g      = (const float*)d_in[5];
    const float* b_g      = (const float*)d_in[6];
    const float* w_final  = (const float*)d_in[7];
    const float* b_final  = (const float*)d_in[8];
    const float* bn_gamma = (const float*)d_in[9];
    const float* bn_beta  = (const float*)d_in[10];
    const float* bn_mean  = (const float*)d_in[11];
    const float* bn_var   = (const float*)d_in[12];
    float* out = (float*)d_out;

    dim3 pgrid(NNq / 128, BB);
    proj_kernel<OFF_Q ><<<pgrid, 256>>>(x, w_theta, b_theta);
    proj_kernel<OFF_PF><<<pgrid, 256>>>(x, w_phi,   b_phi);
    proj_kernel<OFF_GF><<<pgrid, 256>>>(x, w_g,     b_g);

    pool_kernel<<<(BB * N2 * CI) / 256, 256>>>();

    static bool attn_attr_set = false;
    if (!attn_attr_set) {
        cudaFuncSetAttribute(attn_kernel,
                             cudaFuncAttributeMaxDynamicSharedMemorySize,
                             SM_BYTES);
        attn_attr_set = true;
    }
    dim3 agrid(NNq / 256, BB);
    attn_kernel<<<agrid, 256, SM_BYTES>>>();

    dim3 fgrid(NNq / 128, CC / 128, BB);
    final_kernel<<<fgrid, 256>>>(w_final, b_final, bn_gamma, bn_beta,
                                 bn_mean, bn_var, x, out);
}